// round 7
// baseline (speedup 1.0000x reference)
#include <cuda_runtime.h>
#include <cstdint>
#include <climits>

// out = self_tensor; out[sorted_index[i], :] += value[i, :]
// N=262144 rows, M=1048576 updates, D=128 cols, fp32. sorted_index SORTED,
// delivered as int32 by the harness.
//
// SINGLE fused kernel, value-centric, zero atomics, CHUNK=8:
//   warp w owns idx chunk [i0, i1) = [8w, 8w+8) -> 131072 warps (4x R6's
//   parallelism, ~14 waves on 148 SMs for load balance). Lanes 0..7 load the
//   chunk indices; ballot marks run starts. The warp owns output rows
//   (idx[i0-1], idx[i1-1]]:
//     - run starting in-chunk: out[b] = self[b] + sum(value[run]) (last run
//       may extend past i1 -> short L2-hit idx scan)
//     - gap rows between runs: out[r] = self[r], 2-deep batched for MLP
//     - last warp copies the tail (idx[M-1], N)
//   Runs partition value; gaps partition untouched rows -> minimal 776MB
//   traffic, one launch, no CSR scratch, no atomics.

static constexpr int D4 = 32;     // 128 floats = 32 float4/row
static constexpr int CHUNK = 8;   // idx entries per warp

__global__ void fused_scatter_add_kernel(const float* __restrict__ self_t,
                                         const float* __restrict__ value,
                                         const int* __restrict__ idx,
                                         float* __restrict__ out,
                                         int n_rows, int m) {
    const unsigned FULL = 0xffffffffu;
    const int warp = (blockIdx.x * blockDim.x + threadIdx.x) >> 5;
    const int lane = threadIdx.x & 31;

    const int i0 = warp * CHUNK;
    if (i0 >= m) return;
    const int i1 = (i0 + CHUNK < m) ? i0 + CHUNK : m;
    const int valid = i1 - i0;

    const float4* __restrict__ selfv = reinterpret_cast<const float4*>(self_t);
    const float4* __restrict__ valv  = reinterpret_cast<const float4*>(value);
    float4* __restrict__ outv        = reinterpret_cast<float4*>(out);

    // lanes 0..valid-1 hold the chunk indices
    int my = INT_MAX;
    if (lane < valid) my = __ldg(&idx[i0 + lane]);
    const int a = (i0 > 0) ? __ldg(&idx[i0 - 1]) : -1;   // entry before chunk

    int left = __shfl_up_sync(FULL, my, 1);
    if (lane == 0) left = a;
    unsigned mask = __ballot_sync(FULL, (my != left) && (lane < valid));

    int prev = a;
    unsigned rem = mask;
    while (rem) {
        const int p = __ffs(rem) - 1;
        rem &= rem - 1;
        const int b   = __shfl_sync(FULL, my, p);
        const int nxt = rem ? (__ffs(rem) - 1) : valid;

        // copy-only rows in the gap (prev, b), 2-deep batched
        {
            int r = prev + 1;
            for (; r + 1 < b; r += 2) {
                float4 c0 = __ldcs(&selfv[(size_t)r * D4 + lane]);
                float4 c1 = __ldcs(&selfv[(size_t)(r + 1) * D4 + lane]);
                __stcs(&outv[(size_t)r * D4 + lane], c0);
                __stcs(&outv[(size_t)(r + 1) * D4 + lane], c1);
            }
            if (r < b) {
                float4 c0 = __ldcs(&selfv[(size_t)r * D4 + lane]);
                __stcs(&outv[(size_t)r * D4 + lane], c0);
            }
        }

        // accumulate run of row b: in-chunk part [i0+p, i0+nxt)
        float4 acc = __ldcs(&selfv[(size_t)b * D4 + lane]);
        const float4* pv = valv + (size_t)(i0 + p) * D4 + lane;
        int n = nxt - p;
        while (n >= 4) {
            float4 v0 = __ldcs(pv);
            float4 v1 = __ldcs(pv + D4);
            float4 v2 = __ldcs(pv + 2 * D4);
            float4 v3 = __ldcs(pv + 3 * D4);
            acc.x += v0.x; acc.y += v0.y; acc.z += v0.z; acc.w += v0.w;
            acc.x += v1.x; acc.y += v1.y; acc.z += v1.z; acc.w += v1.w;
            acc.x += v2.x; acc.y += v2.y; acc.z += v2.z; acc.w += v2.w;
            acc.x += v3.x; acc.y += v3.y; acc.z += v3.z; acc.w += v3.w;
            pv += 4 * D4; n -= 4;
        }
        if (n >= 2) {
            float4 v0 = __ldcs(pv);
            float4 v1 = __ldcs(pv + D4);
            acc.x += v0.x; acc.y += v0.y; acc.z += v0.z; acc.w += v0.w;
            acc.x += v1.x; acc.y += v1.y; acc.z += v1.z; acc.w += v1.w;
            pv += 2 * D4; n -= 2;
        }
        if (n) {
            float4 v = __ldcs(pv);
            acc.x += v.x; acc.y += v.y; acc.z += v.z; acc.w += v.w;
        }

        // last run in chunk may extend past i1 (short L2-hit scan)
        if (nxt == valid) {
            int j = i1;
            while (j < m && __ldg(&idx[j]) == b) {
                float4 v = __ldcs(&valv[(size_t)j * D4 + lane]);
                acc.x += v.x; acc.y += v.y; acc.z += v.z; acc.w += v.w;
                ++j;
            }
        }

        __stcs(&outv[(size_t)b * D4 + lane], acc);
        prev = b;
    }

    // last warp copies the tail (idx[M-1], N)
    if (i1 == m) {
        int r = prev + 1;
        for (; r + 1 < n_rows; r += 2) {
            float4 c0 = __ldcs(&selfv[(size_t)r * D4 + lane]);
            float4 c1 = __ldcs(&selfv[(size_t)(r + 1) * D4 + lane]);
            __stcs(&outv[(size_t)r * D4 + lane], c0);
            __stcs(&outv[(size_t)(r + 1) * D4 + lane], c1);
        }
        if (r < n_rows) {
            float4 c0 = __ldcs(&selfv[(size_t)r * D4 + lane]);
            __stcs(&outv[(size_t)r * D4 + lane], c0);
        }
    }
}

extern "C" void kernel_launch(void* const* d_in, const int* in_sizes, int n_in,
                              void* d_out, int out_size) {
    const float* self_t = (const float*)d_in[0];  // (N, 128) fp32
    const float* value  = (const float*)d_in[1];  // (M, 128) fp32
    const int*   idx    = (const int*)d_in[2];    // (M,) sorted
    // d_in[3] = pos, unused

    const int m      = in_sizes[2];       // 1048576
    const int n_rows = out_size / 128;    // 262144

    const int warps   = (m + CHUNK - 1) / CHUNK;   // 131072
    const int threads = 256;                       // 8 warps/block
    const int blocks  = (warps * 32 + threads - 1) / threads;

    fused_scatter_add_kernel<<<blocks, threads>>>(self_t, value, idx,
                                                  (float*)d_out, n_rows, m);
}

// round 8
// speedup vs baseline: 1.0569x; 1.0569x over previous
#include <cuda_runtime.h>
#include <cstdint>

// out = self_tensor; out[sorted_index[i], :] += value[i, :]
// N=262144 rows, M=1048576 updates, D=128 cols, fp32. sorted_index SORTED,
// delivered as int32 by the harness.
//
// Two-kernel champion (R4) + vectorized pass-1:
// Pass 1: CSR row-start offsets (starts[r] = lower_bound(idx, r),
//   starts[N] = M). int4-vectorized: thread t owns idx[4t..4t+3], plus the
//   boundary element idx[4t-1]; fills starts for every run boundary inside
//   its quad. Thread covering the last quad closes the tail.
// Pass 2: one warp per output row; 2 coalesced L1-hit loads of starts,
//   then streams the run of value rows (float4, 4-deep batched) on top of
//   the self row, single store. Zero atomics; minimal 776MB traffic,
//   evict-first hints keep idx/starts L2-resident.

static constexpr int D4 = 32;          // 128 floats = 32 float4/row
static constexpr int MAX_ROWS = 262144;

__device__ int g_starts[MAX_ROWS + 1];

__global__ void build_starts_kernel(const int4* __restrict__ idx4,
                                    const int* __restrict__ idx,
                                    int m, int n_rows) {
    const int t = blockIdx.x * blockDim.x + threadIdx.x;
    const int i0 = t * 4;                  // first idx position of this quad
    if (i0 >= m) return;

    const int4 q = __ldg(&idx4[t]);        // idx[i0..i0+3] (m % 4 == 0)
    const int a = (i0 > 0) ? __ldg(&idx[i0 - 1]) : -1;

    // run boundaries inside the quad: starts[r] = position for r in (prev, cur]
    int prev = a;
    int v;
    v = q.x; for (int r = prev + 1; r <= v; ++r) g_starts[r] = i0;     prev = v;
    v = q.y; for (int r = prev + 1; r <= v; ++r) g_starts[r] = i0 + 1; prev = v;
    v = q.z; for (int r = prev + 1; r <= v; ++r) g_starts[r] = i0 + 2; prev = v;
    v = q.w; for (int r = prev + 1; r <= v; ++r) g_starts[r] = i0 + 3; prev = v;

    if (i0 + 4 >= m) {                      // last quad closes the tail
        for (int r = prev + 1; r <= n_rows; ++r) g_starts[r] = m;
    }
}

__global__ void scatter_add_rows_kernel(const float* __restrict__ self_t,
                                        const float* __restrict__ value,
                                        float* __restrict__ out,
                                        int n_rows) {
    const int warp = (blockIdx.x * blockDim.x + threadIdx.x) >> 5;
    const int lane = threadIdx.x & 31;
    if (warp >= n_rows) return;

    const int r = warp;

    const float4* __restrict__ selfv = reinterpret_cast<const float4*>(self_t);
    const float4* __restrict__ valv  = reinterpret_cast<const float4*>(value);
    float4* __restrict__ outv        = reinterpret_cast<float4*>(out);

    // self row load issued early, overlaps the starts lookup
    float4 acc = __ldcs(&selfv[(size_t)r * D4 + lane]);

    int s = 0;
    if (lane < 2) s = g_starts[r + lane];
    const int start = __shfl_sync(0xffffffffu, s, 0);
    const int end   = __shfl_sync(0xffffffffu, s, 1);

    const float4* p = valv + (size_t)start * D4 + lane;
    int n = end - start;

    while (n >= 4) {
        float4 v0 = __ldcs(p);
        float4 v1 = __ldcs(p + D4);
        float4 v2 = __ldcs(p + 2 * D4);
        float4 v3 = __ldcs(p + 3 * D4);
        acc.x += v0.x; acc.y += v0.y; acc.z += v0.z; acc.w += v0.w;
        acc.x += v1.x; acc.y += v1.y; acc.z += v1.z; acc.w += v1.w;
        acc.x += v2.x; acc.y += v2.y; acc.z += v2.z; acc.w += v2.w;
        acc.x += v3.x; acc.y += v3.y; acc.z += v3.z; acc.w += v3.w;
        p += 4 * D4;
        n -= 4;
    }
    if (n >= 2) {
        float4 v0 = __ldcs(p);
        float4 v1 = __ldcs(p + D4);
        acc.x += v0.x; acc.y += v0.y; acc.z += v0.z; acc.w += v0.w;
        acc.x += v1.x; acc.y += v1.y; acc.z += v1.z; acc.w += v1.w;
        p += 2 * D4;
        n -= 2;
    }
    if (n) {
        float4 v = __ldcs(p);
        acc.x += v.x; acc.y += v.y; acc.z += v.z; acc.w += v.w;
    }

    __stcs(&outv[(size_t)r * D4 + lane], acc);
}

extern "C" void kernel_launch(void* const* d_in, const int* in_sizes, int n_in,
                              void* d_out, int out_size) {
    const float* self_t = (const float*)d_in[0];  // (N, 128) fp32
    const float* value  = (const float*)d_in[1];  // (M, 128) fp32
    const int*   idx    = (const int*)d_in[2];    // (M,) sorted
    // d_in[3] = pos, unused

    const int m      = in_sizes[2];       // 1048576 (divisible by 4)
    const int n_rows = out_size / 128;    // 262144 (<= MAX_ROWS)

    {
        const int threads = 256;
        const int quads = (m + 3) / 4;                // 262144
        const int blocks = (quads + threads - 1) / threads;
        build_starts_kernel<<<blocks, threads>>>(
            reinterpret_cast<const int4*>(idx), idx, m, n_rows);
    }
    {
        const int threads = 256;          // 8 warps/block
        const int blocks = (n_rows * 32 + threads - 1) / threads;
        scatter_add_rows_kernel<<<blocks, threads>>>(self_t, value,
                                                     (float*)d_out, n_rows);
    }
}

// round 9
// speedup vs baseline: 1.0770x; 1.0190x over previous
#include <cuda_runtime.h>
#include <cstdint>

// out = self_tensor; out[sorted_index[i], :] += value[i, :]
// N=262144 rows, M=1048576 updates, D=128 cols, fp32. sorted_index SORTED,
// delivered as int32 by the harness.
//
// Two-kernel champion (R4 structure):
// Pass 1: CSR row-start offsets (starts[r] = lower_bound(idx, r),
//   starts[N] = M). One load per element: thread i loads idx[i], obtains
//   idx[i-1] via __shfl_up; only lane 0 loads its warp boundary. Thread i
//   fills starts[r] for r in (idx[i-1], idx[i]].
// Pass 2: one warp per output row; 2 coalesced L1-hit loads of starts,
//   then streams the run of value rows (float4, 4-deep batched) on top of
//   the self row, single store. Zero atomics; minimal 776MB traffic,
//   evict-first hints keep idx/starts L2-resident.

static constexpr int D4 = 32;          // 128 floats = 32 float4/row
static constexpr int MAX_ROWS = 262144;

__device__ int g_starts[MAX_ROWS + 1];

__global__ void build_starts_kernel(const int* __restrict__ idx,
                                    int m, int n_rows) {
    const unsigned FULL = 0xffffffffu;
    const int i = blockIdx.x * blockDim.x + threadIdx.x;
    const int lane = threadIdx.x & 31;

    const int b = (i < m) ? __ldg(&idx[i]) : n_rows;   // virtual idx[m] = n
    int a = __shfl_up_sync(FULL, b, 1);
    if (lane == 0)                                     // warp-boundary element
        a = (i > 0) ? __ldg(&idx[i - 1]) : -1;

    if (i > m) return;
    if (i == m) a = (m > 0) ? __ldg(&idx[m - 1]) : -1; // tail closer
    for (int r = a + 1; r <= b; ++r) g_starts[r] = i;
}

__global__ void scatter_add_rows_kernel(const float* __restrict__ self_t,
                                        const float* __restrict__ value,
                                        float* __restrict__ out,
                                        int n_rows) {
    const int warp = (blockIdx.x * blockDim.x + threadIdx.x) >> 5;
    const int lane = threadIdx.x & 31;
    if (warp >= n_rows) return;

    const int r = warp;

    const float4* __restrict__ selfv = reinterpret_cast<const float4*>(self_t);
    const float4* __restrict__ valv  = reinterpret_cast<const float4*>(value);
    float4* __restrict__ outv        = reinterpret_cast<float4*>(out);

    // self row load issued early, overlaps the starts lookup
    float4 acc = __ldcs(&selfv[(size_t)r * D4 + lane]);

    int s = 0;
    if (lane < 2) s = g_starts[r + lane];
    const int start = __shfl_sync(0xffffffffu, s, 0);
    const int end   = __shfl_sync(0xffffffffu, s, 1);

    const float4* p = valv + (size_t)start * D4 + lane;
    int n = end - start;

    while (n >= 4) {
        float4 v0 = __ldcs(p);
        float4 v1 = __ldcs(p + D4);
        float4 v2 = __ldcs(p + 2 * D4);
        float4 v3 = __ldcs(p + 3 * D4);
        acc.x += v0.x; acc.y += v0.y; acc.z += v0.z; acc.w += v0.w;
        acc.x += v1.x; acc.y += v1.y; acc.z += v1.z; acc.w += v1.w;
        acc.x += v2.x; acc.y += v2.y; acc.z += v2.z; acc.w += v2.w;
        acc.x += v3.x; acc.y += v3.y; acc.z += v3.z; acc.w += v3.w;
        p += 4 * D4;
        n -= 4;
    }
    if (n >= 2) {
        float4 v0 = __ldcs(p);
        float4 v1 = __ldcs(p + D4);
        acc.x += v0.x; acc.y += v0.y; acc.z += v0.z; acc.w += v0.w;
        acc.x += v1.x; acc.y += v1.y; acc.z += v1.z; acc.w += v1.w;
        p += 2 * D4;
        n -= 2;
    }
    if (n) {
        float4 v = __ldcs(p);
        acc.x += v.x; acc.y += v.y; acc.z += v.z; acc.w += v.w;
    }

    __stcs(&outv[(size_t)r * D4 + lane], acc);
}

extern "C" void kernel_launch(void* const* d_in, const int* in_sizes, int n_in,
                              void* d_out, int out_size) {
    const float* self_t = (const float*)d_in[0];  // (N, 128) fp32
    const float* value  = (const float*)d_in[1];  // (M, 128) fp32
    const int*   idx    = (const int*)d_in[2];    // (M,) sorted
    // d_in[3] = pos, unused

    const int m      = in_sizes[2];       // 1048576
    const int n_rows = out_size / 128;    // 262144 (<= MAX_ROWS)

    {
        const int threads = 512;
        const int blocks = (m + 1 + threads - 1) / threads;
        build_starts_kernel<<<blocks, threads>>>(idx, m, n_rows);
    }
    {
        const int threads = 256;          // 8 warps/block
        const int blocks = (n_rows * 32 + threads - 1) / threads;
        scatter_add_rows_kernel<<<blocks, threads>>>(self_t, value,
                                                     (float*)d_out, n_rows);
    }
}